// round 6
// baseline (speedup 1.0000x reference)
#include <cuda_runtime.h>
#include <cuda_bf16.h>
#include <math.h>
#include <stdint.h>

#define DIM 4096
#define BSZ 1024
#define NW  12

// gemm1 tiling (BK=32, padded rows of 40)
#define BK1   32
#define NS1   (DIM / BK1)
#define LDT1  40
#define T32   (128 * LDT1 * 2)
// gemm2 tiling (BK=16, padded rows of 24, 3-stage)
#define BK2   16
#define NS2   (DIM / BK2)
#define LDT2  24
#define T16   (128 * LDT2 * 2)
#define G2_STAGE (12 * T16)

// ---------------- device-global scratch ----------------
__device__ __align__(16) __nv_bfloat16 g_Ar_h[(size_t)DIM * DIM];
__device__ __align__(16) __nv_bfloat16 g_Ar_l[(size_t)DIM * DIM];
__device__ __align__(16) __nv_bfloat16 g_Ai_h[(size_t)DIM * DIM];
__device__ __align__(16) __nv_bfloat16 g_Ai_l[(size_t)DIM * DIM];
__device__ __align__(16) __nv_bfloat16 g_Br_h[(size_t)DIM * DIM];
__device__ __align__(16) __nv_bfloat16 g_Br_l[(size_t)DIM * DIM];
__device__ __align__(16) __nv_bfloat16 g_Bi_h[(size_t)DIM * DIM];
__device__ __align__(16) __nv_bfloat16 g_Bi_l[(size_t)DIM * DIM];
__device__ __align__(16) __nv_bfloat16 g_Bp_h[(size_t)DIM * DIM];   // U1re+U1im
__device__ __align__(16) __nv_bfloat16 g_Bp_l[(size_t)DIM * DIM];
__device__ __align__(16) __nv_bfloat16 g_x_h[(size_t)BSZ * DIM];
__device__ __align__(16) __nv_bfloat16 g_x_l[(size_t)BSZ * DIM];
__device__ __align__(16) __nv_bfloat16 g_sr_h[(size_t)BSZ * DIM];
__device__ __align__(16) __nv_bfloat16 g_sr_l[(size_t)BSZ * DIM];
__device__ __align__(16) __nv_bfloat16 g_si_h[(size_t)BSZ * DIM];
__device__ __align__(16) __nv_bfloat16 g_si_l[(size_t)BSZ * DIM];
__device__ __align__(16) __nv_bfloat16 g_sp_h[(size_t)BSZ * DIM];   // re+im
__device__ __align__(16) __nv_bfloat16 g_sp_l[(size_t)BSZ * DIM];
__device__ int   g_perm[DIM];
__device__ float g_norm[BSZ];

// ---------------- helpers ----------------
__device__ __forceinline__ void split_bf(float v, __nv_bfloat16& h, __nv_bfloat16& l) {
    h = __float2bfloat16(v);
    l = __float2bfloat16(v - __bfloat162float(h));
}
__device__ __forceinline__ uint32_t pk(__nv_bfloat16 a, __nv_bfloat16 b) {
    return (uint32_t)__bfloat16_as_ushort(a) | ((uint32_t)__bfloat16_as_ushort(b) << 16);
}
__device__ __forceinline__ void cp16(uint32_t dst, const void* src) {
    asm volatile("cp.async.cg.shared.global [%0], [%1], 16;" :: "r"(dst), "l"(src));
}
#define CP_COMMIT() asm volatile("cp.async.commit_group;" ::: "memory")
#define CP_WAIT2()  asm volatile("cp.async.wait_group 2;" ::: "memory")
#define CP_WAIT1()  asm volatile("cp.async.wait_group 1;" ::: "memory")
#define CP_WAIT0()  asm volatile("cp.async.wait_group 0;" ::: "memory")

__device__ __forceinline__ void ldsm4(uint32_t r[4], uint32_t addr) {
    asm volatile("ldmatrix.sync.aligned.m8n8.x4.shared.b16 {%0,%1,%2,%3}, [%4];"
        : "=r"(r[0]), "=r"(r[1]), "=r"(r[2]), "=r"(r[3]) : "r"(addr));
}
__device__ __forceinline__ void ldsm2(uint32_t r[2], uint32_t addr) {
    asm volatile("ldmatrix.sync.aligned.m8n8.x2.shared.b16 {%0,%1}, [%2];"
        : "=r"(r[0]), "=r"(r[1]) : "r"(addr));
}
__device__ __forceinline__ void mma16816(float c[4], const uint32_t a[4], const uint32_t b[2]) {
    asm volatile("mma.sync.aligned.m16n8k16.row.col.f32.bf16.bf16.f32 "
        "{%0,%1,%2,%3},{%4,%5,%6,%7},{%8,%9},{%0,%1,%2,%3};"
        : "+f"(c[0]), "+f"(c[1]), "+f"(c[2]), "+f"(c[3])
        : "r"(a[0]), "r"(a[1]), "r"(a[2]), "r"(a[3]), "r"(b[0]), "r"(b[1]));
}
#define MMA_BLK(C, A, B) do {                           \
    _Pragma("unroll") for (int _mt = 0; _mt < 4; ++_mt)  \
    _Pragma("unroll") for (int _nt = 0; _nt < 4; ++_nt)  \
        mma16816(C[_mt][_nt], A[_mt], B[_nt]);           \
} while (0)

// 128x32 tile loader (gemm1)
__device__ __forceinline__ void cpa32(const __nv_bfloat16* __restrict__ src,
                                      int row0, int k0, uint32_t smt, int tid) {
#pragma unroll
    for (int it = 0; it < 2; ++it) {
        int c = tid + it * 256;
        int r = c >> 2, kk = (c & 3) << 3;
        cp16(smt + (r * LDT1 + kk) * 2, src + (size_t)(row0 + r) * DIM + k0 + kk);
    }
}
// 128x16 tile loader (gemm2)
__device__ __forceinline__ void cpa16(const __nv_bfloat16* __restrict__ src,
                                      int row0, int k0, uint32_t smt, int tid) {
    int r = tid >> 1, kk = (tid & 1) << 3;
    cp16(smt + (r * LDT2 + kk) * 2, src + (size_t)(row0 + r) * DIM + k0 + kk);
}

// ---------------- prep kernels ----------------
__global__ void perm_kernel() {
    int j = blockIdx.x * blockDim.x + threadIdx.x;
    if (j >= DIM) return;
    int idx = j;
#pragma unroll
    for (int i = NW - 1; i >= 0; --i) {
        int c = i, t = (i + 1) % NW;
        int cb = (idx >> (NW - 1 - c)) & 1;
        idx ^= cb << (NW - 1 - t);
    }
    g_perm[j] = idx;
}

__global__ void norm_kernel(const float* __restrict__ x) {
    int b = blockIdx.x;
    const float4* xr = (const float4*)(x + (size_t)b * DIM);
    float s = 0.f;
    for (int i = threadIdx.x; i < DIM / 4; i += blockDim.x) {
        float4 v = xr[i];
        s += v.x * v.x + v.y * v.y + v.z * v.z + v.w * v.w;
    }
    __shared__ float red[4];
#pragma unroll
    for (int o = 16; o > 0; o >>= 1) s += __shfl_down_sync(0xffffffffu, s, o);
    if ((threadIdx.x & 31) == 0) red[threadIdx.x >> 5] = s;
    __syncthreads();
    if (threadIdx.x == 0) g_norm[b] = sqrtf(red[0] + red[1] + red[2] + red[3]);
}

// use_perm=1: permuted-gather U -> A arrays. use_perm=0: U1 -> B arrays + Bp=re+im.
__global__ void conv_u_kernel(const float* __restrict__ Ure,
                              const float* __restrict__ Uim, int use_perm) {
    int j = blockIdx.x;
    int src = use_perm ? g_perm[j] : j;
    const float2* pr = (const float2*)(Ure + (size_t)src * DIM);
    const float2* pi = (const float2*)(Uim + (size_t)src * DIM);
    uint32_t* drh = (uint32_t*)((use_perm ? g_Ar_h : g_Br_h) + (size_t)j * DIM);
    uint32_t* drl = (uint32_t*)((use_perm ? g_Ar_l : g_Br_l) + (size_t)j * DIM);
    uint32_t* dih = (uint32_t*)((use_perm ? g_Ai_h : g_Bi_h) + (size_t)j * DIM);
    uint32_t* dil = (uint32_t*)((use_perm ? g_Ai_l : g_Bi_l) + (size_t)j * DIM);
    uint32_t* dph = (uint32_t*)(g_Bp_h + (size_t)j * DIM);
    uint32_t* dpl = (uint32_t*)(g_Bp_l + (size_t)j * DIM);
    for (int c = threadIdx.x; c < DIM / 2; c += blockDim.x) {
        float2 v = pr[c];
        float2 w = pi[c];
        __nv_bfloat16 h0, l0, h1, l1;
        split_bf(v.x, h0, l0); split_bf(v.y, h1, l1);
        drh[c] = pk(h0, h1); drl[c] = pk(l0, l1);
        split_bf(w.x, h0, l0); split_bf(w.y, h1, l1);
        dih[c] = pk(h0, h1); dil[c] = pk(l0, l1);
        if (!use_perm) {
            split_bf(v.x + w.x, h0, l0); split_bf(v.y + w.y, h1, l1);
            dph[c] = pk(h0, h1); dpl[c] = pk(l0, l1);
        }
    }
}

__global__ void conv_x_kernel(const float* __restrict__ x) {
    int b = blockIdx.x;
    const float2* px = (const float2*)(x + (size_t)b * DIM);
    uint32_t* dh = (uint32_t*)(g_x_h + (size_t)b * DIM);
    uint32_t* dl = (uint32_t*)(g_x_l + (size_t)b * DIM);
    for (int c = threadIdx.x; c < DIM / 2; c += blockDim.x) {
        float2 v = px[c];
        __nv_bfloat16 h0, l0, h1, l1;
        split_bf(v.x, h0, l0); split_bf(v.y, h1, l1);
        dh[c] = pk(h0, h1); dl[c] = pk(l0, l1);
    }
}

// ---------------------------------------------------------------------------
// GEMM1: s[j,b] = Uperm_re[j,:]·x[b,:] (+ i Uperm_im·x). 3-term split-bf16.
// Epilogue: state -> [b][k] bf16 hi/lo (sr, si, sp = re+im).
// ---------------------------------------------------------------------------
__global__ __launch_bounds__(256, 1) void gemm1_kernel() {
    extern __shared__ char smem[];
    uint32_t sbase = (uint32_t)__cvta_generic_to_shared(smem);
    const int tid = threadIdx.x, lane = tid & 31, wid = tid >> 5;
    const int g = lane >> 2, tg = lane & 3;
    const int wm0 = (wid >> 2) * 64, wn0 = (wid & 3) * 32;
    const int m0 = blockIdx.y * 128, n0 = blockIdx.x * 128;

    float cr[4][4][4], ci[4][4][4];
#pragma unroll
    for (int a = 0; a < 4; ++a)
#pragma unroll
        for (int b = 0; b < 4; ++b)
#pragma unroll
            for (int c = 0; c < 4; ++c) { cr[a][b][c] = 0.f; ci[a][b][c] = 0.f; }

#define G1_LOAD(st, t) do {                                    \
    uint32_t _sb = sbase + (st) * 6 * T32; int _k0 = (t) * BK1; \
    cpa32(g_Ar_h, m0, _k0, _sb + 0 * T32, tid);                 \
    cpa32(g_Ar_l, m0, _k0, _sb + 1 * T32, tid);                 \
    cpa32(g_Ai_h, m0, _k0, _sb + 2 * T32, tid);                 \
    cpa32(g_Ai_l, m0, _k0, _sb + 3 * T32, tid);                 \
    cpa32(g_x_h,  n0, _k0, _sb + 4 * T32, tid);                 \
    cpa32(g_x_l,  n0, _k0, _sb + 5 * T32, tid);                 \
} while (0)

    G1_LOAD(0, 0); CP_COMMIT();
    for (int t = 0; t < NS1; ++t) {
        if (t + 1 < NS1) { G1_LOAD((t + 1) & 1, t + 1); CP_COMMIT(); CP_WAIT1(); }
        else CP_WAIT0();
        __syncthreads();
        uint32_t sb = sbase + (t & 1) * 6 * T32;
        const uint32_t boff = ((wn0 + (lane & 7)) * LDT1 + ((lane >> 3) & 1) * 8) * 2;
        const uint32_t aoff = ((wm0 + (lane & 15)) * LDT1 + (lane >> 4) * 8) * 2;
#pragma unroll
        for (int kk = 0; kk < 2; ++kk) {
            const uint32_t ko = kk * 32;
            uint32_t bh[4][2], bl[4][2];
#pragma unroll
            for (int nt = 0; nt < 4; ++nt) {
                uint32_t o = boff + ko + nt * (8 * LDT1 * 2);
                ldsm2(bh[nt], sb + 4 * T32 + o);
                ldsm2(bl[nt], sb + 5 * T32 + o);
            }
            uint32_t ar[4][4], ai[4][4];
#pragma unroll
            for (int mt = 0; mt < 4; ++mt) {
                uint32_t o = aoff + ko + mt * (16 * LDT1 * 2);
                ldsm4(ar[mt], sb + 0 * T32 + o);
                ldsm4(ai[mt], sb + 2 * T32 + o);
            }
            MMA_BLK(cr, ar, bh);
            MMA_BLK(ci, ai, bh);
            MMA_BLK(cr, ar, bl);
            MMA_BLK(ci, ai, bl);
#pragma unroll
            for (int mt = 0; mt < 4; ++mt) {
                uint32_t o = aoff + ko + mt * (16 * LDT1 * 2);
                ldsm4(ar[mt], sb + 1 * T32 + o);
                ldsm4(ai[mt], sb + 3 * T32 + o);
            }
            MMA_BLK(cr, ar, bh);
            MMA_BLK(ci, ai, bh);
        }
        __syncthreads();
    }
#undef G1_LOAD

#pragma unroll
    for (int mt = 0; mt < 4; ++mt)
#pragma unroll
        for (int nt = 0; nt < 4; ++nt)
#pragma unroll
            for (int c = 0; c < 4; ++c) {
                const int m = m0 + wm0 + mt * 16 + g + ((c >> 1) << 3);
                const int b = n0 + wn0 + nt * 8 + tg * 2 + (c & 1);
                const size_t o = (size_t)b * DIM + m;
                const float re = cr[mt][nt][c], im = ci[mt][nt][c];
                __nv_bfloat16 h, l;
                split_bf(re, h, l);  g_sr_h[o] = h; g_sr_l[o] = l;
                split_bf(im, h, l);  g_si_h[o] = h; g_si_l[o] = l;
                split_bf(re + im, h, l); g_sp_h[o] = h; g_sp_l[o] = l;
            }
}

// ---------------------------------------------------------------------------
// GEMM2 (Karatsuba 3M): T1=Ar·Sr, T2=Ai·Si, T3=(Ar+Ai)·(Sr+Si)
// re = T1 - T2 ; im = T3 - T1 - T2.  3-term split each. BK=16, 3-stage pipe.
// smem arrays: 0 Arh 1 Arl 2 Aih 3 Ail 4 Aph 5 Apl | 6 Srh 7 Srl 8 Sih 9 Sil 10 Sph 11 Spl
// ---------------------------------------------------------------------------
__global__ __launch_bounds__(256, 1) void gemm2_kernel(float* __restrict__ out) {
    extern __shared__ char smem[];
    uint32_t sbase = (uint32_t)__cvta_generic_to_shared(smem);
    const int tid = threadIdx.x, lane = tid & 31, wid = tid >> 5;
    const int g = lane >> 2, tg = lane & 3;
    const int wm0 = (wid >> 2) * 64, wn0 = (wid & 3) * 32;
    const int m0 = blockIdx.y * 128, n0 = blockIdx.x * 128;

    float acc[3][4][4][4];
#pragma unroll
    for (int p = 0; p < 3; ++p)
#pragma unroll
        for (int a = 0; a < 4; ++a)
#pragma unroll
            for (int b = 0; b < 4; ++b)
#pragma unroll
                for (int c = 0; c < 4; ++c) acc[p][a][b][c] = 0.f;

#define G2_LOAD(st, t) do {                                      \
    uint32_t _sb = sbase + (st) * G2_STAGE; int _k0 = (t) * BK2;  \
    cpa16(g_Br_h, m0, _k0, _sb + 0 * T16, tid);                   \
    cpa16(g_Br_l, m0, _k0, _sb + 1 * T16, tid);                   \
    cpa16(g_Bi_h, m0, _k0, _sb + 2 * T16, tid);                   \
    cpa16(g_Bi_l, m0, _k0, _sb + 3 * T16, tid);                   \
    cpa16(g_Bp_h, m0, _k0, _sb + 4 * T16, tid);                   \
    cpa16(g_Bp_l, m0, _k0, _sb + 5 * T16, tid);                   \
    cpa16(g_sr_h, n0, _k0, _sb + 6 * T16, tid);                   \
    cpa16(g_sr_l, n0, _k0, _sb + 7 * T16, tid);                   \
    cpa16(g_si_h, n0, _k0, _sb + 8 * T16, tid);                   \
    cpa16(g_si_l, n0, _k0, _sb + 9 * T16, tid);                   \
    cpa16(g_sp_h, n0, _k0, _sb + 10 * T16, tid);                  \
    cpa16(g_sp_l, n0, _k0, _sb + 11 * T16, tid);                  \
} while (0)

    G2_LOAD(0, 0); CP_COMMIT();
    G2_LOAD(1, 1); CP_COMMIT();
    int stg = 0;
    for (int t = 0; t < NS2; ++t) {
        if (t + 2 < NS2) {
            int ns = stg + 2; if (ns >= 3) ns -= 3;
            G2_LOAD(ns, t + 2); CP_COMMIT(); CP_WAIT2();
        } else if (t + 1 < NS2) CP_WAIT1();
        else CP_WAIT0();
        __syncthreads();
        uint32_t sb = sbase + stg * G2_STAGE;
        const uint32_t aoff = ((lane & 15) * LDT2 + (lane >> 4) * 8) * 2;
        const uint32_t boff = ((lane & 7) * LDT2 + ((lane >> 3) & 1) * 8) * 2;
#pragma unroll
        for (int p = 0; p < 3; ++p) {
            const uint32_t Ah = sb + (2 * p + 0) * T16;
            const uint32_t Al = sb + (2 * p + 1) * T16;
            const uint32_t Bh = sb + (6 + 2 * p) * T16;
            const uint32_t Bl = sb + (7 + 2 * p) * T16;
            uint32_t av[4][4], bh[4][2], bl[4][2];
#pragma unroll
            for (int mt = 0; mt < 4; ++mt)
                ldsm4(av[mt], Ah + aoff + (wm0 + mt * 16) * (LDT2 * 2));
#pragma unroll
            for (int nt = 0; nt < 4; ++nt)
                ldsm2(bh[nt], Bh + boff + (wn0 + nt * 8) * (LDT2 * 2));
            MMA_BLK(acc[p], av, bh);
#pragma unroll
            for (int nt = 0; nt < 4; ++nt)
                ldsm2(bl[nt], Bl + boff + (wn0 + nt * 8) * (LDT2 * 2));
            MMA_BLK(acc[p], av, bl);
#pragma unroll
            for (int mt = 0; mt < 4; ++mt)
                ldsm4(av[mt], Al + aoff + (wm0 + mt * 16) * (LDT2 * 2));
            MMA_BLK(acc[p], av, bh);
        }
        __syncthreads();
        if (++stg == 3) stg = 0;
    }
#undef G2_LOAD

#pragma unroll
    for (int mt = 0; mt < 4; ++mt)
#pragma unroll
        for (int nt = 0; nt < 4; ++nt)
#pragma unroll
            for (int c = 0; c < 4; ++c) {
                const int i = m0 + wm0 + mt * 16 + g + ((c >> 1) << 3);
                const int b = n0 + wn0 + nt * 8 + tg * 2 + (c & 1);
                const float t1 = acc[0][mt][nt][c];
                const float t2 = acc[1][mt][nt][c];
                const float t3 = acc[2][mt][nt][c];
                const float re = t1 - t2;
                const float im = t3 - t1 - t2;
                out[(size_t)b * DIM + i] = sqrtf(re * re + im * im) / g_norm[b];
            }
}

// ---------------------------------------------------------------------------
extern "C" void kernel_launch(void* const* d_in, const int* in_sizes, int n_in,
                              void* d_out, int out_size) {
    const float* x     = (const float*)d_in[0];
    const float* U_re  = (const float*)d_in[1];
    const float* U_im  = (const float*)d_in[2];
    const float* U1_re = (const float*)d_in[3];
    const float* U1_im = (const float*)d_in[4];
    float* out = (float*)d_out;

    cudaFuncSetAttribute(gemm1_kernel, cudaFuncAttributeMaxDynamicSharedMemorySize, 2 * 6 * T32);
    cudaFuncSetAttribute(gemm2_kernel, cudaFuncAttributeMaxDynamicSharedMemorySize, 3 * G2_STAGE);

    perm_kernel<<<DIM / 256, 256>>>();
    norm_kernel<<<BSZ, 128>>>(x);
    conv_u_kernel<<<DIM, 256>>>(U_re, U_im, 1);
    conv_u_kernel<<<DIM, 256>>>(U1_re, U1_im, 0);
    conv_x_kernel<<<BSZ, 256>>>(x);

    dim3 grid(BSZ / 128, DIM / 128);   // (8, 32)
    gemm1_kernel<<<grid, 256, 2 * 6 * T32>>>();
    gemm2_kernel<<<grid, 256, 3 * G2_STAGE>>>(out);
}

// round 7
// speedup vs baseline: 1.2160x; 1.2160x over previous
#include <cuda_runtime.h>
#include <cuda_bf16.h>
#include <math.h>
#include <stdint.h>

#define DIM 4096
#define BSZ 1024
#define NW  12

// shared tiling: BK=32
#define BK   32
#define NS   (DIM / BK)
// gemm1: padded rows (40 elems) like round 5
#define LDT1 40
#define T32  (128 * LDT1 * 2)
// gemm2: unpadded swizzled rows (32 elems = 64B), 12 arrays/stage
#define TS2  (128 * 64)
#define G2S  (12 * TS2)

// ---------------- device-global scratch ----------------
__device__ __align__(16) __nv_bfloat16 g_Ar_h[(size_t)DIM * DIM];
__device__ __align__(16) __nv_bfloat16 g_Ar_l[(size_t)DIM * DIM];
__device__ __align__(16) __nv_bfloat16 g_Ai_h[(size_t)DIM * DIM];
__device__ __align__(16) __nv_bfloat16 g_Ai_l[(size_t)DIM * DIM];
__device__ __align__(16) __nv_bfloat16 g_Br_h[(size_t)DIM * DIM];
__device__ __align__(16) __nv_bfloat16 g_Br_l[(size_t)DIM * DIM];
__device__ __align__(16) __nv_bfloat16 g_Bi_h[(size_t)DIM * DIM];
__device__ __align__(16) __nv_bfloat16 g_Bi_l[(size_t)DIM * DIM];
__device__ __align__(16) __nv_bfloat16 g_Bp_h[(size_t)DIM * DIM];   // U1re+U1im
__device__ __align__(16) __nv_bfloat16 g_Bp_l[(size_t)DIM * DIM];
__device__ __align__(16) __nv_bfloat16 g_x_h[(size_t)BSZ * DIM];
__device__ __align__(16) __nv_bfloat16 g_x_l[(size_t)BSZ * DIM];
__device__ __align__(16) __nv_bfloat16 g_sr_h[(size_t)BSZ * DIM];
__device__ __align__(16) __nv_bfloat16 g_sr_l[(size_t)BSZ * DIM];
__device__ __align__(16) __nv_bfloat16 g_si_h[(size_t)BSZ * DIM];
__device__ __align__(16) __nv_bfloat16 g_si_l[(size_t)BSZ * DIM];
__device__ __align__(16) __nv_bfloat16 g_sp_h[(size_t)BSZ * DIM];   // re+im
__device__ __align__(16) __nv_bfloat16 g_sp_l[(size_t)BSZ * DIM];
__device__ int   g_perm[DIM];
__device__ float g_norm[BSZ];

// ---------------- helpers ----------------
__device__ __forceinline__ void split_bf(float v, __nv_bfloat16& h, __nv_bfloat16& l) {
    h = __float2bfloat16(v);
    l = __float2bfloat16(v - __bfloat162float(h));
}
__device__ __forceinline__ uint32_t pk(__nv_bfloat16 a, __nv_bfloat16 b) {
    return (uint32_t)__bfloat16_as_ushort(a) | ((uint32_t)__bfloat16_as_ushort(b) << 16);
}
__device__ __forceinline__ void cp16(uint32_t dst, const void* src) {
    asm volatile("cp.async.cg.shared.global [%0], [%1], 16;" :: "r"(dst), "l"(src));
}
#define CP_COMMIT() asm volatile("cp.async.commit_group;" ::: "memory")
#define CP_WAIT1()  asm volatile("cp.async.wait_group 1;" ::: "memory")
#define CP_WAIT0()  asm volatile("cp.async.wait_group 0;" ::: "memory")

__device__ __forceinline__ void ldsm4(uint32_t r[4], uint32_t addr) {
    asm volatile("ldmatrix.sync.aligned.m8n8.x4.shared.b16 {%0,%1,%2,%3}, [%4];"
        : "=r"(r[0]), "=r"(r[1]), "=r"(r[2]), "=r"(r[3]) : "r"(addr));
}
__device__ __forceinline__ void ldsm2(uint32_t r[2], uint32_t addr) {
    asm volatile("ldmatrix.sync.aligned.m8n8.x2.shared.b16 {%0,%1}, [%2];"
        : "=r"(r[0]), "=r"(r[1]) : "r"(addr));
}
__device__ __forceinline__ void mma16816(float c[4], const uint32_t a[4], const uint32_t b[2]) {
    asm volatile("mma.sync.aligned.m16n8k16.row.col.f32.bf16.bf16.f32 "
        "{%0,%1,%2,%3},{%4,%5,%6,%7},{%8,%9},{%0,%1,%2,%3};"
        : "+f"(c[0]), "+f"(c[1]), "+f"(c[2]), "+f"(c[3])
        : "r"(a[0]), "r"(a[1]), "r"(a[2]), "r"(a[3]), "r"(b[0]), "r"(b[1]));
}
#define MMA_BLK(C, A, B) do {                           \
    _Pragma("unroll") for (int _mt = 0; _mt < 4; ++_mt)  \
    _Pragma("unroll") for (int _nt = 0; _nt < 4; ++_nt)  \
        mma16816(C[_mt][_nt], A[_mt], B[_nt]);           \
} while (0)

// gemm1 loader: 128x32 into padded (LDT1) layout
__device__ __forceinline__ void cpa32(const __nv_bfloat16* __restrict__ src,
                                      int row0, int k0, uint32_t smt, int tid) {
#pragma unroll
    for (int it = 0; it < 2; ++it) {
        int c = tid + it * 256;
        int r = c >> 2, kk = (c & 3) << 3;
        cp16(smt + (r * LDT1 + kk) * 2, src + (size_t)(row0 + r) * DIM + k0 + kk);
    }
}
// gemm2 loader: 128x32 into swizzled unpadded layout (row=64B, chunk^=(r>>1)&3)
__device__ __forceinline__ void cpa32s(const __nv_bfloat16* __restrict__ src,
                                       int row0, int k0, uint32_t smt, int tid) {
#pragma unroll
    for (int it = 0; it < 2; ++it) {
        int c = tid + it * 256;
        int r = c >> 2, ch = c & 3;
        cp16(smt + r * 64 + (((ch ^ ((r >> 1) & 3))) << 4),
             src + (size_t)(row0 + r) * DIM + k0 + ch * 8);
    }
}

// ---------------- prep kernels ----------------
__global__ void perm_kernel() {
    int j = blockIdx.x * blockDim.x + threadIdx.x;
    if (j >= DIM) return;
    int idx = j;
#pragma unroll
    for (int i = NW - 1; i >= 0; --i) {
        int c = i, t = (i + 1) % NW;
        int cb = (idx >> (NW - 1 - c)) & 1;
        idx ^= cb << (NW - 1 - t);
    }
    g_perm[j] = idx;
}

__global__ void norm_kernel(const float* __restrict__ x) {
    int b = blockIdx.x;
    const float4* xr = (const float4*)(x + (size_t)b * DIM);
    float s = 0.f;
    for (int i = threadIdx.x; i < DIM / 4; i += blockDim.x) {
        float4 v = xr[i];
        s += v.x * v.x + v.y * v.y + v.z * v.z + v.w * v.w;
    }
    __shared__ float red[4];
#pragma unroll
    for (int o = 16; o > 0; o >>= 1) s += __shfl_down_sync(0xffffffffu, s, o);
    if ((threadIdx.x & 31) == 0) red[threadIdx.x >> 5] = s;
    __syncthreads();
    if (threadIdx.x == 0) g_norm[b] = sqrtf(red[0] + red[1] + red[2] + red[3]);
}

// use_perm=1: permuted gather U -> A arrays. use_perm=0: U1 -> B arrays + Bp.
__global__ void conv_u_kernel(const float* __restrict__ Ure,
                              const float* __restrict__ Uim, int use_perm) {
    int j = blockIdx.x;
    int src = use_perm ? g_perm[j] : j;
    const float2* pr = (const float2*)(Ure + (size_t)src * DIM);
    const float2* pi = (const float2*)(Uim + (size_t)src * DIM);
    uint32_t* drh = (uint32_t*)((use_perm ? g_Ar_h : g_Br_h) + (size_t)j * DIM);
    uint32_t* drl = (uint32_t*)((use_perm ? g_Ar_l : g_Br_l) + (size_t)j * DIM);
    uint32_t* dih = (uint32_t*)((use_perm ? g_Ai_h : g_Bi_h) + (size_t)j * DIM);
    uint32_t* dil = (uint32_t*)((use_perm ? g_Ai_l : g_Bi_l) + (size_t)j * DIM);
    uint32_t* dph = (uint32_t*)(g_Bp_h + (size_t)j * DIM);
    uint32_t* dpl = (uint32_t*)(g_Bp_l + (size_t)j * DIM);
    for (int c = threadIdx.x; c < DIM / 2; c += blockDim.x) {
        float2 v = pr[c];
        float2 w = pi[c];
        __nv_bfloat16 h0, l0, h1, l1;
        split_bf(v.x, h0, l0); split_bf(v.y, h1, l1);
        drh[c] = pk(h0, h1); drl[c] = pk(l0, l1);
        split_bf(w.x, h0, l0); split_bf(w.y, h1, l1);
        dih[c] = pk(h0, h1); dil[c] = pk(l0, l1);
        if (!use_perm) {
            split_bf(v.x + w.x, h0, l0); split_bf(v.y + w.y, h1, l1);
            dph[c] = pk(h0, h1); dpl[c] = pk(l0, l1);
        }
    }
}

__global__ void conv_x_kernel(const float* __restrict__ x) {
    int b = blockIdx.x;
    const float2* px = (const float2*)(x + (size_t)b * DIM);
    uint32_t* dh = (uint32_t*)(g_x_h + (size_t)b * DIM);
    uint32_t* dl = (uint32_t*)(g_x_l + (size_t)b * DIM);
    for (int c = threadIdx.x; c < DIM / 2; c += blockDim.x) {
        float2 v = px[c];
        __nv_bfloat16 h0, l0, h1, l1;
        split_bf(v.x, h0, l0); split_bf(v.y, h1, l1);
        dh[c] = pk(h0, h1); dl[c] = pk(l0, l1);
    }
}

// ---------------------------------------------------------------------------
// GEMM1 (round-5 structure): s[j,b] = Uperm·x. Epilogue -> sr, si, sp=re+im.
// ---------------------------------------------------------------------------
__global__ __launch_bounds__(256, 1) void gemm1_kernel() {
    extern __shared__ char smem[];
    uint32_t sbase = (uint32_t)__cvta_generic_to_shared(smem);
    const int tid = threadIdx.x, lane = tid & 31, wid = tid >> 5;
    const int g = lane >> 2, tg = lane & 3;
    const int wm0 = (wid >> 2) * 64, wn0 = (wid & 3) * 32;
    const int m0 = blockIdx.y * 128, n0 = blockIdx.x * 128;

    float cr[4][4][4], ci[4][4][4];
#pragma unroll
    for (int a = 0; a < 4; ++a)
#pragma unroll
        for (int b = 0; b < 4; ++b)
#pragma unroll
            for (int c = 0; c < 4; ++c) { cr[a][b][c] = 0.f; ci[a][b][c] = 0.f; }

#define G1_LOAD(st, t) do {                                    \
    uint32_t _sb = sbase + (st) * 6 * T32; int _k0 = (t) * BK;  \
    cpa32(g_Ar_h, m0, _k0, _sb + 0 * T32, tid);                 \
    cpa32(g_Ar_l, m0, _k0, _sb + 1 * T32, tid);                 \
    cpa32(g_Ai_h, m0, _k0, _sb + 2 * T32, tid);                 \
    cpa32(g_Ai_l, m0, _k0, _sb + 3 * T32, tid);                 \
    cpa32(g_x_h,  n0, _k0, _sb + 4 * T32, tid);                 \
    cpa32(g_x_l,  n0, _k0, _sb + 5 * T32, tid);                 \
} while (0)

    G1_LOAD(0, 0); CP_COMMIT();
    for (int t = 0; t < NS; ++t) {
        if (t + 1 < NS) { G1_LOAD((t + 1) & 1, t + 1); CP_COMMIT(); CP_WAIT1(); }
        else CP_WAIT0();
        __syncthreads();
        uint32_t sb = sbase + (t & 1) * 6 * T32;
        const uint32_t boff = ((wn0 + (lane & 7)) * LDT1 + ((lane >> 3) & 1) * 8) * 2;
        const uint32_t aoff = ((wm0 + (lane & 15)) * LDT1 + (lane >> 4) * 8) * 2;
#pragma unroll
        for (int kk = 0; kk < 2; ++kk) {
            const uint32_t ko = kk * 32;
            uint32_t bh[4][2], bl[4][2];
#pragma unroll
            for (int nt = 0; nt < 4; ++nt) {
                uint32_t o = boff + ko + nt * (8 * LDT1 * 2);
                ldsm2(bh[nt], sb + 4 * T32 + o);
                ldsm2(bl[nt], sb + 5 * T32 + o);
            }
            uint32_t ar[4][4], ai[4][4];
#pragma unroll
            for (int mt = 0; mt < 4; ++mt) {
                uint32_t o = aoff + ko + mt * (16 * LDT1 * 2);
                ldsm4(ar[mt], sb + 0 * T32 + o);
                ldsm4(ai[mt], sb + 2 * T32 + o);
            }
            MMA_BLK(cr, ar, bh);
            MMA_BLK(ci, ai, bh);
            MMA_BLK(cr, ar, bl);
            MMA_BLK(ci, ai, bl);
#pragma unroll
            for (int mt = 0; mt < 4; ++mt) {
                uint32_t o = aoff + ko + mt * (16 * LDT1 * 2);
                ldsm4(ar[mt], sb + 1 * T32 + o);
                ldsm4(ai[mt], sb + 3 * T32 + o);
            }
            MMA_BLK(cr, ar, bh);
            MMA_BLK(ci, ai, bh);
        }
        __syncthreads();
    }
#undef G1_LOAD

#pragma unroll
    for (int mt = 0; mt < 4; ++mt)
#pragma unroll
        for (int nt = 0; nt < 4; ++nt)
#pragma unroll
            for (int c = 0; c < 4; ++c) {
                const int m = m0 + wm0 + mt * 16 + g + ((c >> 1) << 3);
                const int b = n0 + wn0 + nt * 8 + tg * 2 + (c & 1);
                const size_t o = (size_t)b * DIM + m;
                const float re = cr[mt][nt][c], im = ci[mt][nt][c];
                __nv_bfloat16 h, l;
                split_bf(re, h, l);  g_sr_h[o] = h; g_sr_l[o] = l;
                split_bf(im, h, l);  g_si_h[o] = h; g_si_l[o] = l;
                split_bf(re + im, h, l); g_sp_h[o] = h; g_sp_l[o] = l;
            }
}

// ---------------------------------------------------------------------------
// GEMM2 (Karatsuba 3M, BK=32, swizzled smem):
// T1=Br·Sr, T2=Bi·Si, T3=Bp·Sp ; re=T1-T2, im=T3-T1-T2.
// arrays: 0 Brh 1 Brl 2 Bih 3 Bil 4 Bph 5 Bpl | 6 Srh 7 Srl 8 Sih 9 Sil 10 Sph 11 Spl
// ---------------------------------------------------------------------------
__global__ __launch_bounds__(256, 1) void gemm2_kernel(float* __restrict__ out) {
    extern __shared__ char smem[];
    uint32_t sbase = (uint32_t)__cvta_generic_to_shared(smem);
    const int tid = threadIdx.x, lane = tid & 31, wid = tid >> 5;
    const int g = lane >> 2, tg = lane & 3;
    const int wm0 = (wid >> 2) * 64, wn0 = (wid & 3) * 32;
    const int m0 = blockIdx.y * 128, n0 = blockIdx.x * 128;

    float acc[3][4][4][4];
#pragma unroll
    for (int p = 0; p < 3; ++p)
#pragma unroll
        for (int a = 0; a < 4; ++a)
#pragma unroll
            for (int b = 0; b < 4; ++b)
#pragma unroll
                for (int c = 0; c < 4; ++c) acc[p][a][b][c] = 0.f;

    // per-thread swizzled base offsets (row*64 and xor nibble)
    uint32_t apre[4], axor[4], bpre[4], bxor[4];
#pragma unroll
    for (int mt = 0; mt < 4; ++mt) {
        int r = wm0 + mt * 16 + (lane & 15);
        apre[mt] = r * 64;
        axor[mt] = ((r >> 1) & 3) << 4;
    }
#pragma unroll
    for (int nt = 0; nt < 4; ++nt) {
        int r = wn0 + nt * 8 + (lane & 7);
        bpre[nt] = r * 64;
        bxor[nt] = ((r >> 1) & 3) << 4;
    }
    const uint32_t ahalf = (lane >> 4) << 4;        // 0 or 16
    const uint32_t bhalf = ((lane >> 3) & 1) << 4;  // 0 or 16

#define G2_LOAD(st, t) do {                                      \
    uint32_t _sb = sbase + (st) * G2S; int _k0 = (t) * BK;        \
    cpa32s(g_Br_h, m0, _k0, _sb + 0 * TS2, tid);                  \
    cpa32s(g_Br_l, m0, _k0, _sb + 1 * TS2, tid);                  \
    cpa32s(g_Bi_h, m0, _k0, _sb + 2 * TS2, tid);                  \
    cpa32s(g_Bi_l, m0, _k0, _sb + 3 * TS2, tid);                  \
    cpa32s(g_Bp_h, m0, _k0, _sb + 4 * TS2, tid);                  \
    cpa32s(g_Bp_l, m0, _k0, _sb + 5 * TS2, tid);                  \
    cpa32s(g_sr_h, n0, _k0, _sb + 6 * TS2, tid);                  \
    cpa32s(g_sr_l, n0, _k0, _sb + 7 * TS2, tid);                  \
    cpa32s(g_si_h, n0, _k0, _sb + 8 * TS2, tid);                  \
    cpa32s(g_si_l, n0, _k0, _sb + 9 * TS2, tid);                  \
    cpa32s(g_sp_h, n0, _k0, _sb + 10 * TS2, tid);                 \
    cpa32s(g_sp_l, n0, _k0, _sb + 11 * TS2, tid);                 \
} while (0)

    G2_LOAD(0, 0); CP_COMMIT();
    for (int t = 0; t < NS; ++t) {
        if (t + 1 < NS) { G2_LOAD((t + 1) & 1, t + 1); CP_COMMIT(); CP_WAIT1(); }
        else CP_WAIT0();
        __syncthreads();
        uint32_t sb = sbase + (t & 1) * G2S;
#pragma unroll
        for (int kk = 0; kk < 2; ++kk) {
            const uint32_t ko = kk * 32;
#pragma unroll
            for (int p = 0; p < 3; ++p) {
                const uint32_t Ah = sb + (2 * p + 0) * TS2;
                const uint32_t Al = sb + (2 * p + 1) * TS2;
                const uint32_t Bh = sb + (6 + 2 * p) * TS2;
                const uint32_t Bl = sb + (7 + 2 * p) * TS2;
                uint32_t av[4][4], bv[4][2];
#pragma unroll
                for (int mt = 0; mt < 4; ++mt)
                    ldsm4(av[mt], Ah + apre[mt] + ((ko + ahalf) ^ axor[mt]));
#pragma unroll
                for (int nt = 0; nt < 4; ++nt)
                    ldsm2(bv[nt], Bh + bpre[nt] + ((ko + bhalf) ^ bxor[nt]));
                MMA_BLK(acc[p], av, bv);
#pragma unroll
                for (int nt = 0; nt < 4; ++nt)
                    ldsm2(bv[nt], Bl + bpre[nt] + ((ko + bhalf) ^ bxor[nt]));
                MMA_BLK(acc[p], av, bv);
#pragma unroll
                for (int mt = 0; mt < 4; ++mt)
                    ldsm4(av[mt], Al + apre[mt] + ((ko + ahalf) ^ axor[mt]));
#pragma unroll
                for (int nt = 0; nt < 4; ++nt)
                    ldsm2(bv[nt], Bh + bpre[nt] + ((ko + bhalf) ^ bxor[nt]));
                MMA_BLK(acc[p], av, bv);
            }
        }
        __syncthreads();
    }
#undef G2_LOAD

#pragma unroll
    for (int mt = 0; mt < 4; ++mt)
#pragma unroll
        for (int nt = 0; nt < 4; ++nt)
#pragma unroll
            for (int c = 0; c < 4; ++c) {
                const int i = m0 + wm0 + mt * 16 + g + ((c >> 1) << 3);
                const int b = n0 + wn0 + nt * 8 + tg * 2 + (c & 1);
                const float t1 = acc[0][mt][nt][c];
                const float t2 = acc[1][mt][nt][c];
                const float t3 = acc[2][mt][nt][c];
                const float re = t1 - t2;
                const float im = t3 - t1 - t2;
                out[(size_t)b * DIM + i] = sqrtf(re * re + im * im) / g_norm[b];
            }
}

// ---------------------------------------------------------------------------
extern "C" void kernel_launch(void* const* d_in, const int* in_sizes, int n_in,
                              void* d_out, int out_size) {
    const float* x     = (const float*)d_in[0];
    const float* U_re  = (const float*)d_in[1];
    const float* U_im  = (const float*)d_in[2];
    const float* U1_re = (const float*)d_in[3];
    const float* U1_im = (const float*)d_in[4];
    float* out = (float*)d_out;

    cudaFuncSetAttribute(gemm1_kernel, cudaFuncAttributeMaxDynamicSharedMemorySize, 2 * 6 * T32);
    cudaFuncSetAttribute(gemm2_kernel, cudaFuncAttributeMaxDynamicSharedMemorySize, 2 * G2S);

    perm_kernel<<<DIM / 256, 256>>>();
    norm_kernel<<<BSZ, 128>>>(x);
    conv_u_kernel<<<DIM, 256>>>(U_re, U_im, 1);
    conv_u_kernel<<<DIM, 256>>>(U1_re, U1_im, 0);
    conv_x_kernel<<<BSZ, 256>>>(x);

    dim3 grid(BSZ / 128, DIM / 128);   // (8, 32)
    gemm1_kernel<<<grid, 256, 2 * 6 * T32>>>();
    gemm2_kernel<<<grid, 256, 2 * G2S>>>(out);
}

// round 8
// speedup vs baseline: 1.9210x; 1.5798x over previous
#include <cuda_runtime.h>
#include <cuda_bf16.h>
#include <math.h>
#include <stdint.h>

#define DIM 4096
#define BSZ 1024
#define NW  12
#define BK  32                 // fp32 elems per tile row = 128B
#define NS  (DIM / BK)
#define TS  (128 * 128)        // bytes per 128x32 fp32 tile
#define G1S (3 * TS)           // gemm1 stage: Ar, Ai, X
#define G2S (6 * TS)           // gemm2 stage: Br, Bi, Bp, Sr, Si, Sp

// ---------------- device-global scratch (tf32-rounded fp32) ----------------
__device__ __align__(16) float g_Ar[(size_t)DIM * DIM];   // permuted U_re
__device__ __align__(16) float g_Ai[(size_t)DIM * DIM];   // permuted U_im
__device__ __align__(16) float g_Br[(size_t)DIM * DIM];   // U1_re
__device__ __align__(16) float g_Bi[(size_t)DIM * DIM];   // U1_im
__device__ __align__(16) float g_Bp[(size_t)DIM * DIM];   // U1_re+U1_im
__device__ __align__(16) float g_x [(size_t)BSZ * DIM];
__device__ __align__(16) float g_sr[(size_t)BSZ * DIM];   // state re  [b][k]
__device__ __align__(16) float g_si[(size_t)BSZ * DIM];   // state im
__device__ __align__(16) float g_sp[(size_t)BSZ * DIM];   // re+im
__device__ int   g_perm[DIM];
__device__ float g_norm[BSZ];

// ---------------- helpers ----------------
__device__ __forceinline__ float tf32r(float v) {
    uint32_t u;
    asm("cvt.rna.tf32.f32 %0, %1;" : "=r"(u) : "f"(v));
    return __uint_as_float(u);
}
__device__ __forceinline__ void cp16(uint32_t dst, const void* src) {
    asm volatile("cp.async.cg.shared.global [%0], [%1], 16;" :: "r"(dst), "l"(src));
}
#define CP_COMMIT() asm volatile("cp.async.commit_group;" ::: "memory")
#define CP_WAIT1()  asm volatile("cp.async.wait_group 1;" ::: "memory")
#define CP_WAIT0()  asm volatile("cp.async.wait_group 0;" ::: "memory")

__device__ __forceinline__ void ldsm4(uint32_t r[4], uint32_t addr) {
    asm volatile("ldmatrix.sync.aligned.m8n8.x4.shared.b16 {%0,%1,%2,%3}, [%4];"
        : "=r"(r[0]), "=r"(r[1]), "=r"(r[2]), "=r"(r[3]) : "r"(addr));
}
__device__ __forceinline__ void ldsm2(uint32_t r[2], uint32_t addr) {
    asm volatile("ldmatrix.sync.aligned.m8n8.x2.shared.b16 {%0,%1}, [%2];"
        : "=r"(r[0]), "=r"(r[1]) : "r"(addr));
}
__device__ __forceinline__ void mma_tf32(float c[4], const uint32_t a[4], const uint32_t b[2]) {
    asm volatile("mma.sync.aligned.m16n8k8.row.col.f32.tf32.tf32.f32 "
        "{%0,%1,%2,%3},{%4,%5,%6,%7},{%8,%9},{%0,%1,%2,%3};"
        : "+f"(c[0]), "+f"(c[1]), "+f"(c[2]), "+f"(c[3])
        : "r"(a[0]), "r"(a[1]), "r"(a[2]), "r"(a[3]), "r"(b[0]), "r"(b[1]));
}
#define MMA_BLK(C, A, B) do {                            \
    _Pragma("unroll") for (int _mt = 0; _mt < 4; ++_mt)   \
    _Pragma("unroll") for (int _nt = 0; _nt < 4; ++_nt)   \
        mma_tf32(C[_mt][_nt], A[_mt], B[_nt]);            \
} while (0)

// 128x32 fp32 tile, 128B rows, XOR-swizzled 16B chunks (ch ^= r&7)
__device__ __forceinline__ void cpaf(const float* __restrict__ src,
                                     int row0, int k0, uint32_t smt, int tid) {
#pragma unroll
    for (int it = 0; it < 4; ++it) {
        int c = tid + it * 256;
        int r = c >> 3, ch = c & 7;
        cp16(smt + r * 128 + ((ch ^ (r & 7)) << 4),
             src + (size_t)(row0 + r) * DIM + k0 + ch * 4);
    }
}

// ---------------- prep kernels ----------------
__global__ void perm_kernel() {
    int j = blockIdx.x * blockDim.x + threadIdx.x;
    if (j >= DIM) return;
    int idx = j;
#pragma unroll
    for (int i = NW - 1; i >= 0; --i) {
        int c = i, t = (i + 1) % NW;
        int cb = (idx >> (NW - 1 - c)) & 1;
        idx ^= cb << (NW - 1 - t);
    }
    g_perm[j] = idx;   // out_state[j] = in_state[perm[j]]
}

__global__ void norm_kernel(const float* __restrict__ x) {
    int b = blockIdx.x;
    const float4* xr = (const float4*)(x + (size_t)b * DIM);
    float s = 0.f;
    for (int i = threadIdx.x; i < DIM / 4; i += blockDim.x) {
        float4 v = xr[i];
        s += v.x * v.x + v.y * v.y + v.z * v.z + v.w * v.w;
    }
    __shared__ float red[4];
#pragma unroll
    for (int o = 16; o > 0; o >>= 1) s += __shfl_down_sync(0xffffffffu, s, o);
    if ((threadIdx.x & 31) == 0) red[threadIdx.x >> 5] = s;
    __syncthreads();
    if (threadIdx.x == 0) g_norm[b] = sqrtf(red[0] + red[1] + red[2] + red[3]);
}

// use_perm=1: permuted row-gather U -> Ar/Ai. use_perm=0: U1 -> Br/Bi/Bp.
__global__ void conv_u_kernel(const float* __restrict__ Ure,
                              const float* __restrict__ Uim, int use_perm) {
    int j = blockIdx.x;
    int src = use_perm ? g_perm[j] : j;
    const float4* pr = (const float4*)(Ure + (size_t)src * DIM);
    const float4* pi = (const float4*)(Uim + (size_t)src * DIM);
    float4* dr = (float4*)((use_perm ? g_Ar : g_Br) + (size_t)j * DIM);
    float4* di = (float4*)((use_perm ? g_Ai : g_Bi) + (size_t)j * DIM);
    float4* dp = (float4*)(g_Bp + (size_t)j * DIM);
    for (int c = threadIdx.x; c < DIM / 4; c += blockDim.x) {
        float4 v = pr[c];
        float4 w = pi[c];
        float4 o;
        o.x = tf32r(v.x); o.y = tf32r(v.y); o.z = tf32r(v.z); o.w = tf32r(v.w);
        dr[c] = o;
        float4 q;
        q.x = tf32r(w.x); q.y = tf32r(w.y); q.z = tf32r(w.z); q.w = tf32r(w.w);
        di[c] = q;
        if (!use_perm) {
            float4 p;
            p.x = tf32r(v.x + w.x); p.y = tf32r(v.y + w.y);
            p.z = tf32r(v.z + w.z); p.w = tf32r(v.w + w.w);
            dp[c] = p;
        }
    }
}

__global__ void conv_x_kernel(const float* __restrict__ x) {
    int b = blockIdx.x;
    const float4* px = (const float4*)(x + (size_t)b * DIM);
    float4* dh = (float4*)(g_x + (size_t)b * DIM);
    for (int c = threadIdx.x; c < DIM / 4; c += blockDim.x) {
        float4 v = px[c];
        float4 o;
        o.x = tf32r(v.x); o.y = tf32r(v.y); o.z = tf32r(v.z); o.w = tf32r(v.w);
        dh[c] = o;
    }
}

// ---------------------------------------------------------------------------
// GEMM1 (tf32): s[j,b] = Uperm_re[j,:]·x[b,:] (+ i Uperm_im·x).
// Epilogue: tf32-rounded sr, si, sp=re+im stored [b][k].
// smem arrays: 0 Ar, 1 Ai, 2 X.
// ---------------------------------------------------------------------------
__global__ __launch_bounds__(256, 1) void gemm1_kernel() {
    extern __shared__ char smem[];
    uint32_t sbase = (uint32_t)__cvta_generic_to_shared(smem);
    const int tid = threadIdx.x, lane = tid & 31, wid = tid >> 5;
    const int g = lane >> 2, tg = lane & 3;
    const int wm0 = (wid >> 2) * 64, wn0 = (wid & 3) * 32;
    const int m0 = blockIdx.y * 128, n0 = blockIdx.x * 128;

    float cr[4][4][4], ci[4][4][4];
#pragma unroll
    for (int a = 0; a < 4; ++a)
#pragma unroll
        for (int b = 0; b < 4; ++b)
#pragma unroll
            for (int c = 0; c < 4; ++c) { cr[a][b][c] = 0.f; ci[a][b][c] = 0.f; }

    uint32_t apre[4], axor[4], bpre[4], bxor[4];
#pragma unroll
    for (int mt = 0; mt < 4; ++mt) {
        int r = wm0 + mt * 16 + (lane & 15);
        apre[mt] = r * 128;
        axor[mt] = (r & 7) << 4;
    }
#pragma unroll
    for (int nt = 0; nt < 4; ++nt) {
        int r = wn0 + nt * 8 + (lane & 7);
        bpre[nt] = r * 128;
        bxor[nt] = (r & 7) << 4;
    }
    const uint32_t ahalf = (lane >> 4) << 4;
    const uint32_t bhalf = ((lane >> 3) & 1) << 4;

#define G1_LOAD(st, t) do {                                \
    uint32_t _sb = sbase + (st) * G1S; int _k0 = (t) * BK;  \
    cpaf(g_Ar, m0, _k0, _sb + 0 * TS, tid);                 \
    cpaf(g_Ai, m0, _k0, _sb + 1 * TS, tid);                 \
    cpaf(g_x,  n0, _k0, _sb + 2 * TS, tid);                 \
} while (0)

    G1_LOAD(0, 0); CP_COMMIT();
    for (int t = 0; t < NS; ++t) {
        if (t + 1 < NS) { G1_LOAD((t + 1) & 1, t + 1); CP_COMMIT(); CP_WAIT1(); }
        else CP_WAIT0();
        __syncthreads();
        uint32_t sb = sbase + (t & 1) * G1S;
#pragma unroll
        for (int j = 0; j < 4; ++j) {                 // 4 k8 steps per k32
            const uint32_t ko = j * 32;
            uint32_t bv[4][2], av[4][4];
#pragma unroll
            for (int nt = 0; nt < 4; ++nt)
                ldsm2(bv[nt], sb + 2 * TS + bpre[nt] + ((ko + bhalf) ^ bxor[nt]));
#pragma unroll
            for (int mt = 0; mt < 4; ++mt)
                ldsm4(av[mt], sb + 0 * TS + apre[mt] + ((ko + ahalf) ^ axor[mt]));
            MMA_BLK(cr, av, bv);
#pragma unroll
            for (int mt = 0; mt < 4; ++mt)
                ldsm4(av[mt], sb + 1 * TS + apre[mt] + ((ko + ahalf) ^ axor[mt]));
            MMA_BLK(ci, av, bv);
        }
        __syncthreads();
    }
#undef G1_LOAD

#pragma unroll
    for (int mt = 0; mt < 4; ++mt)
#pragma unroll
        for (int nt = 0; nt < 4; ++nt)
#pragma unroll
            for (int c = 0; c < 4; ++c) {
                const int m = m0 + wm0 + mt * 16 + g + ((c >> 1) << 3);
                const int b = n0 + wn0 + nt * 8 + tg * 2 + (c & 1);
                const size_t o = (size_t)b * DIM + m;
                const float re = cr[mt][nt][c], im = ci[mt][nt][c];
                g_sr[o] = tf32r(re);
                g_si[o] = tf32r(im);
                g_sp[o] = tf32r(re + im);
            }
}

// ---------------------------------------------------------------------------
// GEMM2 (tf32, Karatsuba 3M): T1=Br·Sr, T2=Bi·Si, T3=Bp·Sp
// re = T1-T2, im = T3-T1-T2 ; out = |.|/norm.
// smem arrays: 0 Br, 1 Bi, 2 Bp, 3 Sr, 4 Si, 5 Sp.
// ---------------------------------------------------------------------------
__global__ __launch_bounds__(256, 1) void gemm2_kernel(float* __restrict__ out) {
    extern __shared__ char smem[];
    uint32_t sbase = (uint32_t)__cvta_generic_to_shared(smem);
    const int tid = threadIdx.x, lane = tid & 31, wid = tid >> 5;
    const int g = lane >> 2, tg = lane & 3;
    const int wm0 = (wid >> 2) * 64, wn0 = (wid & 3) * 32;
    const int m0 = blockIdx.y * 128, n0 = blockIdx.x * 128;

    float acc[3][4][4][4];
#pragma unroll
    for (int p = 0; p < 3; ++p)
#pragma unroll
        for (int a = 0; a < 4; ++a)
#pragma unroll
            for (int b = 0; b < 4; ++b)
#pragma unroll
                for (int c = 0; c < 4; ++c) acc[p][a][b][c] = 0.f;

    uint32_t apre[4], axor[4], bpre[4], bxor[4];
#pragma unroll
    for (int mt = 0; mt < 4; ++mt) {
        int r = wm0 + mt * 16 + (lane & 15);
        apre[mt] = r * 128;
        axor[mt] = (r & 7) << 4;
    }
#pragma unroll
    for (int nt = 0; nt < 4; ++nt) {
        int r = wn0 + nt * 8 + (lane & 7);
        bpre[nt] = r * 128;
        bxor[nt] = (r & 7) << 4;
    }
    const uint32_t ahalf = (lane >> 4) << 4;
    const uint32_t bhalf = ((lane >> 3) & 1) << 4;

#define G2_LOAD(st, t) do {                                \
    uint32_t _sb = sbase + (st) * G2S; int _k0 = (t) * BK;  \
    cpaf(g_Br, m0, _k0, _sb + 0 * TS, tid);                 \
    cpaf(g_Bi, m0, _k0, _sb + 1 * TS, tid);                 \
    cpaf(g_Bp, m0, _k0, _sb + 2 * TS, tid);                 \
    cpaf(g_sr, n0, _k0, _sb + 3 * TS, tid);                 \
    cpaf(g_si, n0, _k0, _sb + 4 * TS, tid);                 \
    cpaf(g_sp, n0, _k0, _sb + 5 * TS, tid);                 \
} while (0)

    G2_LOAD(0, 0); CP_COMMIT();
    for (int t = 0; t < NS; ++t) {
        if (t + 1 < NS) { G2_LOAD((t + 1) & 1, t + 1); CP_COMMIT(); CP_WAIT1(); }
        else CP_WAIT0();
        __syncthreads();
        uint32_t sb = sbase + (t & 1) * G2S;
#pragma unroll
        for (int j = 0; j < 4; ++j) {
            const uint32_t ko = j * 32;
#pragma unroll
            for (int p = 0; p < 3; ++p) {
                uint32_t av[4][4], bv[4][2];
#pragma unroll
                for (int mt = 0; mt < 4; ++mt)
                    ldsm4(av[mt], sb + p * TS + apre[mt] + ((ko + ahalf) ^ axor[mt]));
#pragma unroll
                for (int nt = 0; nt < 4; ++nt)
                    ldsm2(bv[nt], sb + (3 + p) * TS + bpre[nt] + ((ko + bhalf) ^ bxor[nt]));
                MMA_BLK(acc[p], av, bv);
            }
        }
        __syncthreads();
    }
#undef G2_LOAD

#pragma unroll
    for (int mt = 0; mt < 4; ++mt)
#pragma unroll
        for (int nt = 0; nt < 4; ++nt)
#pragma unroll
            for (int c = 0; c < 4; ++c) {
                const int i = m0 + wm0 + mt * 16 + g + ((c >> 1) << 3);
                const int b = n0 + wn0 + nt * 8 + tg * 2 + (c & 1);
                const float t1 = acc[0][mt][nt][c];
                const float t2 = acc[1][mt][nt][c];
                const float t3 = acc[2][mt][nt][c];
                const float re = t1 - t2;
                const float im = t3 - t1 - t2;
                out[(size_t)b * DIM + i] = sqrtf(re * re + im * im) / g_norm[b];
            }
}

// ---------------------------------------------------------------------------
extern "C" void kernel_launch(void* const* d_in, const int* in_sizes, int n_in,
                              void* d_out, int out_size) {
    const float* x     = (const float*)d_in[0];
    const float* U_re  = (const float*)d_in[1];
    const float* U_im  = (const float*)d_in[2];
    const float* U1_re = (const float*)d_in[3];
    const float* U1_im = (const float*)d_in[4];
    float* out = (float*)d_out;

    cudaFuncSetAttribute(gemm1_kernel, cudaFuncAttributeMaxDynamicSharedMemorySize, 2 * G1S);
    cudaFuncSetAttribute(gemm2_kernel, cudaFuncAttributeMaxDynamicSharedMemorySize, 2 * G2S);

    perm_kernel<<<DIM / 256, 256>>>();
    norm_kernel<<<BSZ, 128>>>(x);
    conv_u_kernel<<<DIM, 256>>>(U_re, U_im, 1);
    conv_u_kernel<<<DIM, 256>>>(U1_re, U1_im, 0);
    conv_x_kernel<<<BSZ, 256>>>(x);

    dim3 grid(BSZ / 128, DIM / 128);   // (8, 32)
    gemm1_kernel<<<grid, 256, 2 * G1S>>>();
    gemm2_kernel<<<grid, 256, 2 * G2S>>>(out);
}